// round 4
// baseline (speedup 1.0000x reference)
#include <cuda_runtime.h>

#define T_STEPS 8192
#define NRES    2048
#define DIN     64
#define DOUT    64
#define GRID_R  128
#define TPB_R   512
#define RPB     16      // reservoir rows per CTA (= warps per CTA)

// ---------------- static scratch (no allocations allowed) ----------------
__device__ float        g_drive[T_STEPS * NRES];        // 64 MB
__device__ float        g_states[(T_STEPS + 1) * NRES]; // 64 MB + 8KB ; g_states[0]=s0=0
__device__ unsigned int g_bar;

// ---------------- helpers ----------------
__device__ __forceinline__ unsigned ld_acq(const unsigned int* p) {
    unsigned v;
    asm volatile("ld.acquire.gpu.global.u32 %0, [%1];" : "=r"(v) : "l"(p));
    return v;
}

__device__ __forceinline__ void red_release_add(unsigned int* p, unsigned v) {
    asm volatile("red.release.gpu.global.add.u32 [%0], %1;" :: "l"(p), "r"(v) : "memory");
}

// packed fp32x2 FMA: d = a*b + c lanewise on {lo,hi} — maps to SASS FFMA2
__device__ __forceinline__ void fma_f32x2(unsigned long long& d,
                                          unsigned long long a,
                                          unsigned long long b,
                                          unsigned long long c) {
    asm("fma.rn.f32x2 %0, %1, %2, %3;" : "=l"(d) : "l"(a), "l"(b), "l"(c));
}

__device__ __forceinline__ float tanh_fast(float x) {
    // 1 - 2/(e^{2x}+1) ; handles +-inf saturation naturally
    float e = __expf(2.0f * x);
    return 1.0f - __fdividef(2.0f, e + 1.0f);
}

// ---------------- init: zero barrier counter + s0 ----------------
__global__ void init_kernel() {
    int i = blockIdx.x * blockDim.x + threadIdx.x;
    if (i == 0) g_bar = 0u;
    if (i < NRES) g_states[i] = 0.0f;
}

// ---------------- drive = u @ W_in^T + 0.01*noise ----------------
// block: 256 threads, 32 t-rows. Loop over n in tiles of 64.
__global__ void drive_kernel(const float* __restrict__ u,
                             const float* __restrict__ noise,
                             const float* __restrict__ Win) {
    __shared__ float u_sm[32 * 68];   // padded stride 68 to break bank conflicts
    __shared__ float w_sm[64 * 64];
    __shared__ float o_sm[32 * 64];

    int tid = threadIdx.x;
    int t0  = blockIdx.x * 32;

    // load u rows (32x64, contiguous in gmem), into padded smem
    for (int e = tid * 4; e < 32 * 64; e += 256 * 4) {
        int row = e >> 6, col = e & 63;
        float4 v = *(const float4*)(u + (t0 + row) * DIN + col);
        *(float4*)&u_sm[row * 68 + col] = v;
    }

    int tp = tid & 31;   // t row within tile
    int og = tid >> 5;   // output-group (8 n's each); constant per warp -> w broadcast

    for (int nt = 0; nt < NRES / 64; nt++) {
        __syncthreads();
        // load W_in rows [nt*64, nt*64+64) : 64x64 contiguous
        for (int e = tid * 4; e < 64 * 64; e += 256 * 4) {
            *(float4*)&w_sm[e] = *(const float4*)(Win + nt * 64 * DIN + e);
        }
        __syncthreads();

        float acc[8];
#pragma unroll
        for (int oi = 0; oi < 8; oi++) acc[oi] = 0.0f;
#pragma unroll
        for (int k4 = 0; k4 < 16; k4++) {
            float4 uv = *(const float4*)&u_sm[tp * 68 + k4 * 4];
#pragma unroll
            for (int oi = 0; oi < 8; oi++) {
                float4 wv = *(const float4*)&w_sm[(og * 8 + oi) * 64 + k4 * 4];
                acc[oi] += uv.x * wv.x + uv.y * wv.y + uv.z * wv.z + uv.w * wv.w;
            }
        }
#pragma unroll
        for (int oi = 0; oi < 8; oi++) o_sm[tp * 64 + og * 8 + oi] = acc[oi];
        __syncthreads();

        // coalesced write-out + noise add
        for (int e = tid * 4; e < 32 * 64; e += 256 * 4) {
            int row = e >> 6, col = e & 63;
            int gidx = (t0 + row) * NRES + nt * 64 + col;
            float4 nv = *(const float4*)(noise + gidx);
            float4 ov = *(const float4*)&o_sm[e];
            float4 dv;
            dv.x = ov.x + 0.01f * nv.x;
            dv.y = ov.y + 0.01f * nv.y;
            dv.z = ov.z + 0.01f * nv.z;
            dv.w = ov.w + 0.01f * nv.w;
            *(float4*)&g_drive[gidx] = dv;
        }
    }
}

// ---------------- persistent reservoir recurrence ----------------
// 128 CTAs x 512 threads. CTA b owns rows [16b, 16b+16).
// Warp w owns columns [128w, 128w+128). Lane l: row r = l&15, col-half g = l>>4.
// Lane holds 64 W values as 32 packed f32x2 registers. s broadcast from SMEM
// (dual copy, bank-shifted). Inner product via packed fma.rn.f32x2 (FFMA2).
__global__ void __launch_bounds__(TPB_R, 1)
reservoir_kernel(const float* __restrict__ Wm) {
    __shared__ float s_dup[2 * NRES + 4];  // copy A @0, copy B @ NRES+4 (bank shift)
    __shared__ float part[RPB * 17];       // [row][warp] padded

    const int tid = threadIdx.x;
    const int w   = tid >> 5;
    const int l   = tid & 31;
    const int g   = l >> 4;
    const int r   = l & 15;
    const int b   = blockIdx.x;

    const int lane_row = b * RPB + r;      // global row this lane's W belongs to
    const int myrow    = b * RPB + w;      // global row this warp finalizes

    // ---- preload W slice into packed registers (32 x f32x2 per lane) ----
    unsigned long long wreg[32];
    {
        const float* wrow = Wm + (size_t)lane_row * NRES + w * 128 + g * 64;
#pragma unroll
        for (int j = 0; j < 16; j++) {
            ulonglong2 v = *(const ulonglong2*)(wrow + 4 * j);
            wreg[2 * j + 0] = v.x;
            wreg[2 * j + 1] = v.y;
        }
    }

    const float* sbase = s_dup + (g ? (NRES + 4 + w * 128 + 64) : (w * 128));
    unsigned bar_target = 0;

    for (int t = 0; t < T_STEPS; t++) {
        // ---- broadcast s_t into SMEM (both copies), L1-bypassed ----
        float4 sv = __ldcg((const float4*)(g_states + (size_t)t * NRES) + tid);
        *(float4*)(s_dup + 4 * tid)            = sv;
        *(float4*)(s_dup + NRES + 4 + 4 * tid) = sv;

        // prefetch drive for this warp's output row
        float dval = 0.0f;
        if (l == 0) dval = __ldg(&g_drive[(size_t)t * NRES + myrow]);
        __syncthreads();

        // ---- matvec: 32 packed FMAs/lane, s via broadcast LDS.128 ----
        unsigned long long a01 = 0ull, a23 = 0ull;   // packed (0.0f, 0.0f)
#pragma unroll
        for (int j = 0; j < 16; j++) {
            ulonglong2 s2 = *(const ulonglong2*)(sbase + 4 * j);
            fma_f32x2(a01, wreg[2 * j + 0], s2.x, a01);
            fma_f32x2(a23, wreg[2 * j + 1], s2.y, a23);
        }
        float2 f01 = *(float2*)&a01;
        float2 f23 = *(float2*)&a23;
        float acc = (f01.x + f01.y) + (f23.x + f23.y);
        // combine the two column-halves of the same row
        acc += __shfl_xor_sync(0xffffffffu, acc, 16);
        if (l < 16) part[l * 17 + w] = acc;   // part[row][warp]
        __syncthreads();

        // ---- warp w finalizes row myrow ----
        float y = (l < 16) ? part[w * 17 + l] : 0.0f;
        y += __shfl_down_sync(0xffffffffu, y, 8);
        y += __shfl_down_sync(0xffffffffu, y, 4);
        y += __shfl_down_sync(0xffffffffu, y, 2);
        y += __shfl_down_sync(0xffffffffu, y, 1);
        if (l == 0) {
            float sold = s_dup[myrow];
            float sn = 0.7f * sold + 0.3f * tanh_fast(dval + y);
            g_states[(size_t)(t + 1) * NRES + myrow] = sn;
        }
        __syncthreads();   // CTA-scope release: all 16 row-stores ordered before arrival

        // ---- global barrier (monotonic counter; release-arrive / acquire-spin) ----
        bar_target += GRID_R;
        if (tid == 0) {
            red_release_add(&g_bar, 1u);          // cumulative: publishes CTA's stores
            while (ld_acq(&g_bar) < bar_target) { }
        }
        __syncthreads();
    }
}

// ---------------- out = states @ w_out^T + b_out ----------------
// block: 256 threads, 32 t-rows, k-tiles of 64.
__global__ void out_kernel(const float* __restrict__ wout,
                           const float* __restrict__ bout,
                           float* __restrict__ out) {
    __shared__ float s_sm[32 * 68];
    __shared__ float w_sm[64 * 64];

    int tid = threadIdx.x;
    int t0  = blockIdx.x * 32;
    int tp  = tid & 31;
    int og  = tid >> 5;

    float acc[8];
#pragma unroll
    for (int oi = 0; oi < 8; oi++) acc[oi] = 0.0f;

    for (int kt = 0; kt < NRES / 64; kt++) {
        __syncthreads();
        // states tile: rows t0..t0+31 (shifted by +1), cols kt*64..+64
        for (int e = tid * 4; e < 32 * 64; e += 256 * 4) {
            int row = e >> 6, col = e & 63;
            float4 v = *(const float4*)(&g_states[(size_t)(t0 + row + 1) * NRES + kt * 64 + col]);
            *(float4*)&s_sm[row * 68 + col] = v;
        }
        // w_out tile: 64 outputs x 64 k
        for (int e = tid * 4; e < 64 * 64; e += 256 * 4) {
            int row = e >> 6, col = e & 63;
            *(float4*)&w_sm[row * 64 + col] =
                *(const float4*)(&wout[(size_t)row * NRES + kt * 64 + col]);
        }
        __syncthreads();

#pragma unroll
        for (int k4 = 0; k4 < 16; k4++) {
            float4 sv = *(const float4*)&s_sm[tp * 68 + k4 * 4];
#pragma unroll
            for (int oi = 0; oi < 8; oi++) {
                float4 wv = *(const float4*)&w_sm[(og * 8 + oi) * 64 + k4 * 4];
                acc[oi] += sv.x * wv.x + sv.y * wv.y + sv.z * wv.z + sv.w * wv.w;
            }
        }
    }

#pragma unroll
    for (int oi = 0; oi < 8; oi++) {
        int o = og * 8 + oi;
        out[(size_t)(t0 + tp) * DOUT + o] = acc[oi] + bout[o];
    }
}

// ---------------- launch ----------------
extern "C" void kernel_launch(void* const* d_in, const int* in_sizes, int n_in,
                              void* d_out, int out_size) {
    (void)in_sizes; (void)n_in; (void)out_size;
    const float* u     = (const float*)d_in[0];
    const float* noise = (const float*)d_in[1];
    const float* Win   = (const float*)d_in[2];
    const float* Wm    = (const float*)d_in[3];
    const float* wout  = (const float*)d_in[4];
    const float* bout  = (const float*)d_in[5];
    float* out = (float*)d_out;

    init_kernel<<<8, 256>>>();
    drive_kernel<<<T_STEPS / 32, 256>>>(u, noise, Win);
    reservoir_kernel<<<GRID_R, TPB_R>>>(Wm);
    out_kernel<<<T_STEPS / 32, 256>>>(wout, bout, out);
}

// round 17
// speedup vs baseline: 1.0579x; 1.0579x over previous
#include <cuda_runtime.h>

#define T_STEPS 8192
#define NRES    2048
#define DIN     64
#define DOUT    64
#define GRID_R  128
#define TPB_R   512
#define RPB     16      // reservoir rows per CTA (= warps per CTA)

// ---------------- static scratch (no allocations allowed) ----------------
__device__ float        g_drive[T_STEPS * NRES];        // 64 MB
__device__ float        g_states[(T_STEPS + 1) * NRES]; // 64 MB + 8KB
__device__ unsigned int g_flags[GRID_R * 32];           // per-CTA epoch flags, 128B stride

// ---------------- helpers ----------------
__device__ __forceinline__ unsigned ld_acq(const unsigned int* p) {
    unsigned v;
    asm volatile("ld.acquire.gpu.global.u32 %0, [%1];" : "=r"(v) : "l"(p));
    return v;
}

__device__ __forceinline__ void st_rel(unsigned int* p, unsigned v) {
    asm volatile("st.release.gpu.global.u32 [%0], %1;" :: "l"(p), "r"(v) : "memory");
}

// packed fp32x2 FMA: d = a*b + c lanewise on {lo,hi} — maps to SASS FFMA2
__device__ __forceinline__ void fma_f32x2(unsigned long long& d,
                                          unsigned long long a,
                                          unsigned long long b,
                                          unsigned long long c) {
    asm("fma.rn.f32x2 %0, %1, %2, %3;" : "=l"(d) : "l"(a), "l"(b), "l"(c));
}

__device__ __forceinline__ float tanh_fast(float x) {
    float e = __expf(2.0f * x);
    return 1.0f - __fdividef(2.0f, e + 1.0f);
}

// ---------------- init: zero epoch flags (graph replays reuse them) ----------------
__global__ void init_kernel() {
    int i = blockIdx.x * blockDim.x + threadIdx.x;
    if (i < GRID_R) g_flags[i * 32] = 0u;
}

// ---------------- drive = u @ W_in^T + 0.01*noise ----------------
__global__ void drive_kernel(const float* __restrict__ u,
                             const float* __restrict__ noise,
                             const float* __restrict__ Win) {
    __shared__ float u_sm[32 * 68];
    __shared__ float w_sm[64 * 64];
    __shared__ float o_sm[32 * 64];

    int tid = threadIdx.x;
    int t0  = blockIdx.x * 32;

    for (int e = tid * 4; e < 32 * 64; e += 256 * 4) {
        int row = e >> 6, col = e & 63;
        float4 v = *(const float4*)(u + (t0 + row) * DIN + col);
        *(float4*)&u_sm[row * 68 + col] = v;
    }

    int tp = tid & 31;
    int og = tid >> 5;

    for (int nt = 0; nt < NRES / 64; nt++) {
        __syncthreads();
        for (int e = tid * 4; e < 64 * 64; e += 256 * 4) {
            *(float4*)&w_sm[e] = *(const float4*)(Win + nt * 64 * DIN + e);
        }
        __syncthreads();

        float acc[8];
#pragma unroll
        for (int oi = 0; oi < 8; oi++) acc[oi] = 0.0f;
#pragma unroll
        for (int k4 = 0; k4 < 16; k4++) {
            float4 uv = *(const float4*)&u_sm[tp * 68 + k4 * 4];
#pragma unroll
            for (int oi = 0; oi < 8; oi++) {
                float4 wv = *(const float4*)&w_sm[(og * 8 + oi) * 64 + k4 * 4];
                acc[oi] += uv.x * wv.x + uv.y * wv.y + uv.z * wv.z + uv.w * wv.w;
            }
        }
#pragma unroll
        for (int oi = 0; oi < 8; oi++) o_sm[tp * 64 + og * 8 + oi] = acc[oi];
        __syncthreads();

        for (int e = tid * 4; e < 32 * 64; e += 256 * 4) {
            int row = e >> 6, col = e & 63;
            int gidx = (t0 + row) * NRES + nt * 64 + col;
            float4 nv = *(const float4*)(noise + gidx);
            float4 ov = *(const float4*)&o_sm[e];
            float4 dv;
            dv.x = ov.x + 0.01f * nv.x;
            dv.y = ov.y + 0.01f * nv.y;
            dv.z = ov.z + 0.01f * nv.z;
            dv.w = ov.w + 0.01f * nv.w;
            *(float4*)&g_drive[gidx] = dv;
        }
    }
}

// ---------------- persistent reservoir recurrence ----------------
// 128 CTAs x 512 threads. CTA b produces rows [16b,16b+16) (one per warp).
// Consumer warp w needs only s-columns [128w,128w+128) = producers 8w..8w+7:
// it polls those 8 single-writer epoch flags and loads 16 floats per producer.
// Own-CTA block comes from SMEM; s_old lives in a register on lane 0.
__global__ void __launch_bounds__(TPB_R, 1)
reservoir_kernel(const float* __restrict__ Wm) {
    __shared__ float s_sm[RPB * 264];          // per-warp: copyA @0, copyB @132 (4-bank shift)
    __shared__ float part[RPB * 17];           // [row][warp] padded
    __shared__ __align__(16) float s_next[RPB];// this CTA's 16 fresh values

    const int tid = threadIdx.x;
    const int w   = tid >> 5;
    const int l   = tid & 31;
    const int g   = l >> 4;
    const int r   = l & 15;
    const int b   = blockIdx.x;

    const int lane_row = b * RPB + r;          // row whose W this lane holds
    const int myrow    = b * RPB + w;          // row this warp finalizes
    const int p        = w * 8 + (l >> 2);     // producer CTA this lane tracks
    const int q        = l & 3;                // quarter of that producer's 16 floats
    const bool self    = (p == b);

    float* warpS = s_sm + w * 264;

    // ---- preload W slice into packed registers (32 x f32x2 per lane) ----
    unsigned long long wreg[32];
    {
        const float* wrow = Wm + (size_t)lane_row * NRES + w * 128 + g * 64;
#pragma unroll
        for (int j = 0; j < 16; j++) {
            ulonglong2 v = *(const ulonglong2*)(wrow + 4 * j);
            wreg[2 * j + 0] = v.x;
            wreg[2 * j + 1] = v.y;
        }
    }

    // s_0 = 0: zero both SMEM copies so t=0 matvec yields 0 uniformly
    *(float4*)(warpS + 4 * l)       = make_float4(0.f, 0.f, 0.f, 0.f);
    *(float4*)(warpS + 132 + 4 * l) = make_float4(0.f, 0.f, 0.f, 0.f);
    __syncwarp();

    const float* sbase = warpS + (g ? (132 + 64) : 0);
    unsigned int* pflag = &g_flags[(unsigned)p << 5];
    float sold = 0.0f;                          // valid on lane 0 of each warp

    for (int t = 0; t < T_STEPS; t++) {
        // prefetch drive for this warp's output row (overlaps the wait)
        float dval = 0.0f;
        if (l == 0) dval = __ldg(&g_drive[(size_t)t * NRES + myrow]);

        if (t > 0) {
            float4 sv;
            if (self) {
                sv = *(const float4*)(s_next + 4 * q);      // local, ordered by prior barrier
            } else {
                while (ld_acq(pflag) < (unsigned)t) { }     // 4 lanes/flag coalesce to 1 req
                sv = __ldcg((const float4*)(g_states + (size_t)t * NRES + p * 16 + 4 * q));
            }
            *(float4*)(warpS + 4 * l)       = sv;
            *(float4*)(warpS + 132 + 4 * l) = sv;
            __syncwarp();
        }

        // ---- matvec: 32 packed FMAs/lane over this warp's 128-column slice ----
        unsigned long long a01 = 0ull, a23 = 0ull;
#pragma unroll
        for (int j = 0; j < 16; j++) {
            ulonglong2 s2 = *(const ulonglong2*)(sbase + 4 * j);
            fma_f32x2(a01, wreg[2 * j + 0], s2.x, a01);
            fma_f32x2(a23, wreg[2 * j + 1], s2.y, a23);
        }
        float2 f01 = *(float2*)&a01;
        float2 f23 = *(float2*)&a23;
        float acc = (f01.x + f01.y) + (f23.x + f23.y);
        acc += __shfl_xor_sync(0xffffffffu, acc, 16);       // fold the two column-halves
        if (l < 16) part[l * 17 + w] = acc;
        __syncthreads();

        // ---- warp w finalizes row myrow ----
        float y = (l < 16) ? part[w * 17 + l] : 0.0f;
        y += __shfl_down_sync(0xffffffffu, y, 8);
        y += __shfl_down_sync(0xffffffffu, y, 4);
        y += __shfl_down_sync(0xffffffffu, y, 2);
        y += __shfl_down_sync(0xffffffffu, y, 1);
        if (l == 0) {
            float sn = 0.7f * sold + 0.3f * tanh_fast(dval + y);
            sold = sn;
            g_states[(size_t)(t + 1) * NRES + myrow] = sn;
            s_next[w] = sn;
        }
        __syncthreads();   // orders all 16 row-stores + s_next before the release
        if (tid == 0) st_rel(&g_flags[(unsigned)b << 5], (unsigned)(t + 1));
    }
}

// ---------------- out = states @ w_out^T + b_out ----------------
__global__ void out_kernel(const float* __restrict__ wout,
                           const float* __restrict__ bout,
                           float* __restrict__ out) {
    __shared__ float s_sm[32 * 68];
    __shared__ float w_sm[64 * 64];

    int tid = threadIdx.x;
    int t0  = blockIdx.x * 32;
    int tp  = tid & 31;
    int og  = tid >> 5;

    float acc[8];
#pragma unroll
    for (int oi = 0; oi < 8; oi++) acc[oi] = 0.0f;

    for (int kt = 0; kt < NRES / 64; kt++) {
        __syncthreads();
        for (int e = tid * 4; e < 32 * 64; e += 256 * 4) {
            int row = e >> 6, col = e & 63;
            float4 v = *(const float4*)(&g_states[(size_t)(t0 + row + 1) * NRES + kt * 64 + col]);
            *(float4*)&s_sm[row * 68 + col] = v;
        }
        for (int e = tid * 4; e < 64 * 64; e += 256 * 4) {
            int row = e >> 6, col = e & 63;
            *(float4*)&w_sm[row * 64 + col] =
                *(const float4*)(&wout[(size_t)row * NRES + kt * 64 + col]);
        }
        __syncthreads();

#pragma unroll
        for (int k4 = 0; k4 < 16; k4++) {
            float4 sv = *(const float4*)&s_sm[tp * 68 + k4 * 4];
#pragma unroll
            for (int oi = 0; oi < 8; oi++) {
                float4 wv = *(const float4*)&w_sm[(og * 8 + oi) * 64 + k4 * 4];
                acc[oi] += sv.x * wv.x + sv.y * wv.y + sv.z * wv.z + sv.w * wv.w;
            }
        }
    }

#pragma unroll
    for (int oi = 0; oi < 8; oi++) {
        int o = og * 8 + oi;
        out[(size_t)(t0 + tp) * DOUT + o] = acc[oi] + bout[o];
    }
}

// ---------------- launch ----------------
extern "C" void kernel_launch(void* const* d_in, const int* in_sizes, int n_in,
                              void* d_out, int out_size) {
    (void)in_sizes; (void)n_in; (void)out_size;
    const float* u     = (const float*)d_in[0];
    const float* noise = (const float*)d_in[1];
    const float* Win   = (const float*)d_in[2];
    const float* Wm    = (const float*)d_in[3];
    const float* wout  = (const float*)d_in[4];
    const float* bout  = (const float*)d_in[5];
    float* out = (float*)d_out;

    init_kernel<<<1, 128>>>();
    drive_kernel<<<T_STEPS / 32, 256>>>(u, noise, Win);
    reservoir_kernel<<<GRID_R, TPB_R>>>(Wm);
    out_kernel<<<T_STEPS / 32, 256>>>(wout, bout, out);
}